// round 13
// baseline (speedup 1.0000x reference)
#include <cuda_runtime.h>

#define FULLMASK 0xffffffffu

// ---------------------------------------------------------------------------
// Precomputed per-ring tables (row-independent):
//   g_cs[r][i][lane] = (cos, sin) of angle at k = 32*lane + 31 - i
//                      (lane 0, i==31 holds (c0, s0) for the wrap epilogue)
//   g_cp[r][i][lane] = c_k * P(i),  P(i) = prod_{i'<i} (-s_{k(i')})  (fixup coeff)
//   g_A [r][lane]    = full within-lane product of (-s)
// Lane-minor layout -> conflict-free LDS.
// ---------------------------------------------------------------------------
__device__ float2 g_cs[8][32][32];
__device__ float  g_cp[8][32][32];
__device__ float  g_A[8][32];

// Pinned scalar shared load: prevents hoisting of the 32 fixup coefficients
// into live registers at the point of peak pressure.
static __device__ __forceinline__ float lds_f(unsigned addr) {
    float a; asm volatile("ld.shared.f32 %0, [%1];" : "=f"(a) : "r"(addr)); return a;
}

// ---------------------------------------------------------------------------
// Table precompute: one thread per (ring, lane). Trivial cost.
// ---------------------------------------------------------------------------
__global__ void precompute_tables(const float* __restrict__ ae,
                                  const float* __restrict__ ad) {
    int t = threadIdx.x;
    if (t >= 256) return;
    int r = t >> 5, lane = t & 31;
    const float* ang = (r < 4) ? (ae + r * 1024) : (ad + (r - 4) * 1024);
    float P = 1.0f;
    for (int i = 0; i < 32; i++) {
        int k = lane * 32 + 31 - i;
        float a = ang[k];
        float c = cosf(a), s = sinf(a);
        g_cs[r][i][lane] = make_float2(c, s);
        if (lane == 0 && i == 31) {
            g_cp[r][i][lane] = 0.0f;     // k==0 handled by wrap epilogue
        } else {
            g_cp[r][i][lane] = c * P;
            P *= -s;
        }
    }
    g_A[r][lane] = P;
}

// ---------------------------------------------------------------------------
// One ring applied to a warp's single row held in registers (scalar f32).
// Lane l owns columns [32l, 32l+32).
// Loop-carried chain is a SINGLE FFMA (4 cyc): v = fmaf(-s, v, c*x),
// with c*x and s*x computed off-chain.
// ---------------------------------------------------------------------------
static __device__ __forceinline__ void apply_ring(
    float (&d)[32], int lane,
    const float2* __restrict__ cs,    // &s_cs[r][0][lane], stride 32 float2
    unsigned cp_addr,                 // smem byte addr of s_cp[r][0][lane]
    float Ain)
{
    float x0 = __shfl_sync(FULLMASK, d[0], 0);    // x[0] of the row

    float v   = 0.0f;                             // zero-init carry
    float bnd = 0.0f;                             // boundary output (slot 32l+32)

    #pragma unroll
    for (int i = 0; i < 31; i++) {
        float2 csv = cs[i * 32];
        float xk = d[31 - i];
        float cx = csv.x * xk;                    // off-chain
        float sx = csv.y * xk;                    // off-chain
        float y0 = fmaf(csv.x, v, sx);            // uses old v (off-chain)
        if (i == 0) bnd = y0; else d[32 - i] = y0;
        v = fmaf(-csv.y, v, cx);                  // 4-cyc loop-carried chain
    }
    float2 cs31 = cs[31 * 32];
    float c0 = cs31.x, s0 = cs31.y;               // meaningful only for lane 0
    if (lane != 0) {                              // i == 31 chain step (k = 32*lane)
        float xk = d[0];
        float cx = cs31.x * xk;
        float sx = cs31.y * xk;
        d[1] = fmaf(cs31.x, v, sx);
        v = fmaf(-cs31.y, v, cx);
    }

    // Suffix scan of affine maps F_l(v) = A_l v + B_l over lanes (high -> low).
    float A = Ain, Aown = Ain;
    float q = v;
    float B = v;
    #pragma unroll
    for (int dd = 1; dd < 32; dd <<= 1) {
        float Ao = __shfl_down_sync(FULLMASK, A, dd);
        float Bo = __shfl_down_sync(FULLMASK, B, dd);
        float Bn = fmaf(A, Bo, B);
        float An = A * Ao;
        bool ok = (lane + dd < 32);               // predicated, no branch
        B = ok ? Bn : B;
        A = ok ? An : A;
    }
    float SA = __shfl_down_sync(FULLMASK, A, 1);
    float SB = __shfl_down_sync(FULLMASK, B, 1);
    float V = (lane == 31) ? x0 : fmaf(SA, x0, SB);

    // Fixups: y = y0 + CP * V  (CP row-independent; pinned loads, no hoist)
    bnd = fmaf(lds_f(cp_addr), V, bnd);
    #pragma unroll
    for (int i = 1; i < 32; i++) {
        d[32 - i] = fmaf(lds_f(cp_addr + (unsigned)i * 128u), V, d[32 - i]);
    }

    // Boundary pass: lane l's top output is lane l+1's lowest slot.
    // Lane 31's boundary p = s_{n-1} x_{n-1} + c_{n-1} x_0 feeds lane 0's wrap.
    float p2  = __shfl_sync(FULLMASK, bnd, 31);
    float rec = __shfl_up_sync(FULLMASK, bnd, 1);
    if (lane > 0) {
        d[0] = rec;
    } else {
        float vf = fmaf(Aown, V, q);              // carry_1
        d[0] = fmaf(-s0, vf, c0 * p2);            // y0 = c0 p - s0 carry1
        d[1] = fmaf(c0,  vf, s0 * p2);            // y1 = s0 p + c0 carry1
    }
}

// ---------------------------------------------------------------------------
// Fused kernel, 384 threads = 12 warps, ONE ROW PER WARP, scalar f32.
// __launch_bounds__(384,1): 170-reg cap -- enough for d[32] + hoisted cs
// coefficients WITHOUT spilling (all previous configs pegged their reg cap
// and spilled to local; that local traffic was the L1=53-66% wall).
// 12 warps/SM = 3 warps/SMSP covers the 4-cyc FFMA chain (IPC need ~0.7).
// ---------------------------------------------------------------------------
extern "C" __global__ void __launch_bounds__(384, 1)
enc_dec_kernel(const float* __restrict__ x,
               const float* __restrict__ hw,
               const float* __restrict__ hs,
               float* __restrict__ out, int B)
{
    extern __shared__ unsigned char smem_raw[];
    float2* s_cs = (float2*)smem_raw;                         // 64 KB
    float*  s_A  = (float*)(smem_raw + 65536 + 32768);        // 1 KB
    {
        const float4* g1 = (const float4*)(const void*)g_cs;
        float4* s1 = (float4*)(void*)smem_raw;
        for (int i = threadIdx.x; i < 4096; i += 384) s1[i] = g1[i];
        const float4* g2 = (const float4*)(const void*)g_cp;
        float4* s2 = (float4*)(void*)(smem_raw + 65536);
        for (int i = threadIdx.x; i < 2048; i += 384) s2[i] = g2[i];
        const float4* g3 = (const float4*)(const void*)g_A;
        float4* s3 = (float4*)(void*)(smem_raw + 65536 + 32768);
        for (int i = threadIdx.x; i < 64; i += 384) s3[i] = g3[i];
    }
    __syncthreads();

    int warp = threadIdx.x >> 5;
    int lane = threadIdx.x & 31;

    long long row = (long long)blockIdx.x * 12 + warp;
    if (row >= B) return;                 // partial last block (after the sync)

    unsigned sbase   = (unsigned)__cvta_generic_to_shared(smem_raw);
    unsigned cp_lane = sbase + 65536u + (unsigned)lane * 4u;

    const float* pA = x + row * 1024 + lane * 32;

    // Each lane owns one 128B line (streaming reads, fully consumed).
    float d[32];
    #pragma unroll
    for (int t = 0; t < 8; t++) {
        float4 a = __ldcs((const float4*)(pA + 4 * t));
        d[4 * t + 0] = a.x;
        d[4 * t + 1] = a.y;
        d[4 * t + 2] = a.z;
        d[4 * t + 3] = a.w;
    }

    #pragma unroll 1
    for (int r = 0; r < 4; r++) {
        apply_ring(d, lane, s_cs + r * 1024 + lane,
                   cp_lane + (unsigned)r * 4096u, s_A[r * 32 + lane]);
    }

    // Bottleneck blend: (1-w)*b + w*h, w = sigmoid(hidden_weight[0])
    float hwv = __ldg(hw);
    float w = 1.0f / (1.0f + expf(-hwv));
    float iw = 1.0f - w;
    const float* ph = hs + lane * 32;
    float* ob = out + row * 1024 + lane * 32;
    float* oo = out + (long long)B * 1024 + row * 1024 + lane * 32;

    #pragma unroll
    for (int t = 0; t < 8; t++) {
        float4 h4 = *(const float4*)(ph + 4 * t);
        d[4 * t + 0] = fmaf(iw, d[4 * t + 0], w * h4.x);
        d[4 * t + 1] = fmaf(iw, d[4 * t + 1], w * h4.y);
        d[4 * t + 2] = fmaf(iw, d[4 * t + 2], w * h4.z);
        d[4 * t + 3] = fmaf(iw, d[4 * t + 3], w * h4.w);
        float4 o4 = make_float4(d[4 * t + 0], d[4 * t + 1],
                                d[4 * t + 2], d[4 * t + 3]);
        __stcs((float4*)(ob + 4 * t), o4);
    }

    #pragma unroll 1
    for (int r = 4; r < 8; r++) {
        apply_ring(d, lane, s_cs + r * 1024 + lane,
                   cp_lane + (unsigned)r * 4096u, s_A[r * 32 + lane]);
    }

    #pragma unroll
    for (int t = 0; t < 8; t++) {
        float4 o4 = make_float4(d[4 * t + 0], d[4 * t + 1],
                                d[4 * t + 2], d[4 * t + 3]);
        __stcs((float4*)(oo + 4 * t), o4);
    }
}

// ---------------------------------------------------------------------------
extern "C" void kernel_launch(void* const* d_in, const int* in_sizes, int n_in,
                              void* d_out, int out_size) {
    const float* x  = (const float*)d_in[0];
    const float* ae = (const float*)d_in[1];
    const float* ad = (const float*)d_in[2];
    const float* hw = (const float*)d_in[3];
    const float* hs = (const float*)d_in[4];
    float* out = (float*)d_out;

    int B = in_sizes[0] / 1024;          // 8192
    const int smem_bytes = 65536 + 32768 + 1024;

    precompute_tables<<<1, 256>>>(ae, ad);

    cudaFuncSetAttribute(enc_dec_kernel,
                         cudaFuncAttributeMaxDynamicSharedMemorySize, smem_bytes);
    int blocks = (B + 11) / 12;          // 12 rows per block (12 warps x 1 row)
    enc_dec_kernel<<<blocks, 384, smem_bytes>>>(x, hw, hs, out, B);
}

// round 14
// speedup vs baseline: 1.0783x; 1.0783x over previous
#include <cuda_runtime.h>

#define FULLMASK 0xffffffffu

// ---------------------------------------------------------------------------
// Precomputed per-ring tables (row-independent):
//   g_cs[r][i][lane] = (cos, sin) of angle at k = 32*lane + 31 - i
//                      (lane 0, i==31 holds (c0, s0) for the wrap epilogue)
//   g_cp[r][i][lane] = c_k * P(i),  P(i) = prod_{i'<i} (-s_{k(i')})  (fixup coeff)
//   g_A [r][lane]    = full within-lane product of (-s)
// Lane-minor layout -> conflict-free LDS.
// ---------------------------------------------------------------------------
__device__ float2 g_cs[8][32][32];
__device__ float  g_cp[8][32][32];
__device__ float  g_A[8][32];

// Pinned shared loads (asm volatile): register liveness stays bounded to the
// explicit prefetch distance instead of the compiler's full-loop hoist, which
// is what drove regs to 143 (and to cap-pegged spills in earlier rounds).
static __device__ __forceinline__ void lds_v2(float& a, float& b, unsigned addr) {
    asm volatile("ld.shared.v2.f32 {%0, %1}, [%2];" : "=f"(a), "=f"(b) : "r"(addr));
}
static __device__ __forceinline__ float lds_f(unsigned addr) {
    float a; asm volatile("ld.shared.f32 %0, [%1];" : "=f"(a) : "r"(addr)); return a;
}

// ---------------------------------------------------------------------------
// Table precompute: one thread per (ring, lane). Trivial cost.
// ---------------------------------------------------------------------------
__global__ void precompute_tables(const float* __restrict__ ae,
                                  const float* __restrict__ ad) {
    int t = threadIdx.x;
    if (t >= 256) return;
    int r = t >> 5, lane = t & 31;
    const float* ang = (r < 4) ? (ae + r * 1024) : (ad + (r - 4) * 1024);
    float P = 1.0f;
    for (int i = 0; i < 32; i++) {
        int k = lane * 32 + 31 - i;
        float a = ang[k];
        float c = cosf(a), s = sinf(a);
        g_cs[r][i][lane] = make_float2(c, s);
        if (lane == 0 && i == 31) {
            g_cp[r][i][lane] = 0.0f;     // k==0 handled by wrap epilogue
        } else {
            g_cp[r][i][lane] = c * P;
            P *= -s;
        }
    }
    g_A[r][lane] = P;
}

// ---------------------------------------------------------------------------
// One ring applied to a warp's single row held in registers (scalar f32).
// Lane l owns columns [32l, 32l+32).
// Loop-carried chain is a SINGLE FFMA (4 cyc): v = fmaf(-s, v, c*x).
// cs loads: pinned LDS.64, explicit prefetch distance 2.
// cp loads: pinned LDS.32, prefetch distance 1.
// ---------------------------------------------------------------------------
static __device__ __forceinline__ void apply_ring(
    float (&d)[32], int lane,
    unsigned cs_addr,                 // smem byte addr of s_cs[r][0][lane]
    unsigned cp_addr,                 // smem byte addr of s_cp[r][0][lane]
    float Ain)
{
    float x0 = __shfl_sync(FULLMASK, d[0], 0);    // x[0] of the row

    float v   = 0.0f;                             // zero-init carry
    float bnd = 0.0f;                             // boundary output (slot 32l+32)

    // Prefetch cs[0], cs[1]
    float c0p, s0p, c1p, s1p;
    lds_v2(c0p, s0p, cs_addr);
    lds_v2(c1p, s1p, cs_addr + 256u);

    #pragma unroll
    for (int i = 0; i < 31; i++) {
        float cn = 0.0f, sn = 0.0f;
        if (i < 30) lds_v2(cn, sn, cs_addr + (unsigned)(i + 2) * 256u);
        float xk = d[31 - i];
        float cx = c0p * xk;                      // off-chain
        float sx = s0p * xk;                      // off-chain
        float y0 = fmaf(c0p, v, sx);              // uses old v (off-chain)
        if (i == 0) bnd = y0; else d[32 - i] = y0;
        v = fmaf(-s0p, v, cx);                    // 4-cyc loop-carried chain
        c0p = c1p; s0p = s1p; c1p = cn; s1p = sn;
    }
    // After the loop c0p/s0p hold cs[31].
    float c0 = c0p, s0 = s0p;                     // meaningful only for lane 0
    if (lane != 0) {                              // i == 31 chain step (k = 32*lane)
        float xk = d[0];
        float cx = c0p * xk;
        float sx = s0p * xk;
        d[1] = fmaf(c0p, v, sx);
        v = fmaf(-s0p, v, cx);
    }

    // Suffix scan of affine maps F_l(v) = A_l v + B_l over lanes (high -> low).
    float A = Ain, Aown = Ain;
    float q = v;
    float B = v;
    #pragma unroll
    for (int dd = 1; dd < 32; dd <<= 1) {
        float Ao = __shfl_down_sync(FULLMASK, A, dd);
        float Bo = __shfl_down_sync(FULLMASK, B, dd);
        float Bn = fmaf(A, Bo, B);
        float An = A * Ao;
        bool ok = (lane + dd < 32);               // predicated, no branch
        B = ok ? Bn : B;
        A = ok ? An : A;
    }
    float SA = __shfl_down_sync(FULLMASK, A, 1);
    float SB = __shfl_down_sync(FULLMASK, B, 1);
    float V = (lane == 31) ? x0 : fmaf(SA, x0, SB);

    // Fixups: y = y0 + CP * V  (CP row-independent; pinned, distance-1)
    float cpa = lds_f(cp_addr);
    float cpb = lds_f(cp_addr + 128u);
    bnd = fmaf(cpa, V, bnd);
    #pragma unroll
    for (int i = 1; i < 31; i++) {
        float cpn = lds_f(cp_addr + (unsigned)(i + 1) * 128u);
        d[32 - i] = fmaf(cpb, V, d[32 - i]);
        cpb = cpn;
    }
    d[1] = fmaf(cpb, V, d[1]);                    // cp[31] (0 for lane 0)

    // Boundary pass: lane l's top output is lane l+1's lowest slot.
    // Lane 31's boundary p = s_{n-1} x_{n-1} + c_{n-1} x_0 feeds lane 0's wrap.
    float p2  = __shfl_sync(FULLMASK, bnd, 31);
    float rec = __shfl_up_sync(FULLMASK, bnd, 1);
    if (lane > 0) {
        d[0] = rec;
    } else {
        float vf = fmaf(Aown, V, q);              // carry_1
        d[0] = fmaf(-s0, vf, c0 * p2);            // y0 = c0 p - s0 carry1
        d[1] = fmaf(c0,  vf, s0 * p2);            // y1 = s0 p + c0 carry1
    }
}

// ---------------------------------------------------------------------------
// Fused kernel, 640 threads = 20 warps, ONE ROW PER WARP, scalar f32.
// __launch_bounds__(640,1): 102-reg cap. With both table streams pinned the
// working set is d[32] + prefetch regs + scan temps (~85 regs) -> no spill,
// and 20 warps/SM = 5 warps/SMSP (vs 3 in the 81us run) to fill the
// LDS(29cyc)/SHFL(26cyc) latency gaps that dominate the per-warp path.
// ---------------------------------------------------------------------------
extern "C" __global__ void __launch_bounds__(640, 1)
enc_dec_kernel(const float* __restrict__ x,
               const float* __restrict__ hw,
               const float* __restrict__ hs,
               float* __restrict__ out, int B)
{
    extern __shared__ unsigned char smem_raw[];
    {
        const float4* g1 = (const float4*)(const void*)g_cs;
        float4* s1 = (float4*)(void*)smem_raw;
        for (int i = threadIdx.x; i < 4096; i += 640) s1[i] = g1[i];
        const float4* g2 = (const float4*)(const void*)g_cp;
        float4* s2 = (float4*)(void*)(smem_raw + 65536);
        for (int i = threadIdx.x; i < 2048; i += 640) s2[i] = g2[i];
        const float4* g3 = (const float4*)(const void*)g_A;
        float4* s3 = (float4*)(void*)(smem_raw + 65536 + 32768);
        for (int i = threadIdx.x; i < 64; i += 640) s3[i] = g3[i];
    }
    __syncthreads();

    int warp = threadIdx.x >> 5;
    int lane = threadIdx.x & 31;

    long long row = (long long)blockIdx.x * 20 + warp;
    if (row >= B) return;                 // partial last block (after the sync)

    unsigned sbase   = (unsigned)__cvta_generic_to_shared(smem_raw);
    unsigned cs_lane = sbase + (unsigned)lane * 8u;
    unsigned cp_lane = sbase + 65536u + (unsigned)lane * 4u;
    const float* s_A = (const float*)(smem_raw + 65536 + 32768);

    const float* pA = x + row * 1024 + lane * 32;

    // Each lane owns one 128B line (streaming reads, fully consumed).
    float d[32];
    #pragma unroll
    for (int t = 0; t < 8; t++) {
        float4 a = __ldcs((const float4*)(pA + 4 * t));
        d[4 * t + 0] = a.x;
        d[4 * t + 1] = a.y;
        d[4 * t + 2] = a.z;
        d[4 * t + 3] = a.w;
    }

    #pragma unroll 1
    for (int r = 0; r < 4; r++) {
        apply_ring(d, lane, cs_lane + (unsigned)r * 8192u,
                   cp_lane + (unsigned)r * 4096u, s_A[r * 32 + lane]);
    }

    // Bottleneck blend: (1-w)*b + w*h, w = sigmoid(hidden_weight[0])
    float hwv = __ldg(hw);
    float w = 1.0f / (1.0f + expf(-hwv));
    float iw = 1.0f - w;
    const float* ph = hs + lane * 32;
    float* ob = out + row * 1024 + lane * 32;
    float* oo = out + (long long)B * 1024 + row * 1024 + lane * 32;

    #pragma unroll
    for (int t = 0; t < 8; t++) {
        float4 h4 = *(const float4*)(ph + 4 * t);
        d[4 * t + 0] = fmaf(iw, d[4 * t + 0], w * h4.x);
        d[4 * t + 1] = fmaf(iw, d[4 * t + 1], w * h4.y);
        d[4 * t + 2] = fmaf(iw, d[4 * t + 2], w * h4.z);
        d[4 * t + 3] = fmaf(iw, d[4 * t + 3], w * h4.w);
        float4 o4 = make_float4(d[4 * t + 0], d[4 * t + 1],
                                d[4 * t + 2], d[4 * t + 3]);
        __stcs((float4*)(ob + 4 * t), o4);
    }

    #pragma unroll 1
    for (int r = 4; r < 8; r++) {
        apply_ring(d, lane, cs_lane + (unsigned)r * 8192u,
                   cp_lane + (unsigned)r * 4096u, s_A[r * 32 + lane]);
    }

    #pragma unroll
    for (int t = 0; t < 8; t++) {
        float4 o4 = make_float4(d[4 * t + 0], d[4 * t + 1],
                                d[4 * t + 2], d[4 * t + 3]);
        __stcs((float4*)(oo + 4 * t), o4);
    }
}

// ---------------------------------------------------------------------------
extern "C" void kernel_launch(void* const* d_in, const int* in_sizes, int n_in,
                              void* d_out, int out_size) {
    const float* x  = (const float*)d_in[0];
    const float* ae = (const float*)d_in[1];
    const float* ad = (const float*)d_in[2];
    const float* hw = (const float*)d_in[3];
    const float* hs = (const float*)d_in[4];
    float* out = (float*)d_out;

    int B = in_sizes[0] / 1024;          // 8192
    const int smem_bytes = 65536 + 32768 + 1024;

    precompute_tables<<<1, 256>>>(ae, ad);

    cudaFuncSetAttribute(enc_dec_kernel,
                         cudaFuncAttributeMaxDynamicSharedMemorySize, smem_bytes);
    int blocks = (B + 19) / 20;          // 20 rows per block (20 warps x 1 row)
    enc_dec_kernel<<<blocks, 640, smem_bytes>>>(x, hw, hs, out, B);
}